// round 5
// baseline (speedup 1.0000x reference)
#include <cuda_runtime.h>
#include <cuda_fp16.h>
#include <math.h>

#define NB 16
#define NA 720
#define ND 1024
#define NH 512
#define NW 512
#define PI_F 3.14159265358979323846f

// Filtered sinogram in fp16, PLANAR v / d arrays (16B record per bin = 8 batches).
// g_v[g2][a][bin]  : values v
// g_d[g2][a][bin]  : forward differences d = v[bin+1]-v[bin]
// 16B stride per bin -> warp's ~6.4-bin footprint spans ~1.8 L1 lines per LDG
// (vs 2.75 with interleaved 32B records). 23.6 MB each, both L2-resident.
__device__ uint4 g_v[2 * NA * ND];
__device__ uint4 g_d[2 * NA * ND];

__device__ __forceinline__ float2 cmulf(float2 a, float2 b) {
    return make_float2(a.x * b.x - a.y * b.y, a.x * b.y + a.y * b.x);
}
__device__ __forceinline__ unsigned int h2_as_u32(__half2 h) {
    return *reinterpret_cast<unsigned int*>(&h);
}

// -------------------------------------------------------------------------
// Kernel 1: ramp filter via complex-pair Stockham FFT (filter real & even:
// FFT(u+iv)*f -> re=filt(u), im=filt(v) exactly). Block = (angle a, batch
// pair m). Stores fp16 v and d into the planar arrays (u32 slot p=m&3).
// -------------------------------------------------------------------------
__global__ __launch_bounds__(512) void fbp_filter_kernel(
    const float* __restrict__ sino, const float* __restrict__ filt)
{
    __shared__ float2 bufA[ND];
    __shared__ float2 bufB[ND];
    __shared__ float2 tw[ND / 2];

    const int a = blockIdx.x;
    const int m = blockIdx.y;       // batches 2m, 2m+1
    const int tid = threadIdx.x;

    const float* u = sino + ((size_t)(2 * m) * NA + a) * ND;
    const float* v = sino + ((size_t)(2 * m + 1) * NA + a) * ND;

    bufA[tid]       = make_float2(u[tid],       v[tid]);
    bufA[tid + 512] = make_float2(u[tid + 512], v[tid + 512]);
    {
        float sv, cv;
        sincosf((-2.0f * PI_F / ND) * (float)tid, &sv, &cv);
        tw[tid] = make_float2(cv, sv);
    }
    __syncthreads();

    float2* x = bufA;
    float2* y = bufB;

    #pragma unroll
    for (int stage = 0; stage < 10; ++stage) {
        const int s  = 1 << stage;
        const int q  = tid & (s - 1);
        const int ps = tid - q;
        float2 aa = x[tid];
        float2 bb = x[tid + 512];
        float2 w = tw[ps];
        y[2 * ps + q]     = make_float2(aa.x + bb.x, aa.y + bb.y);
        y[2 * ps + s + q] = cmulf(make_float2(aa.x - bb.x, aa.y - bb.y), w);
        __syncthreads();
        float2* t = x; x = y; y = t;
    }
    {
        float f0 = filt[tid], f1 = filt[tid + 512];
        float2 aa = x[tid];       aa.x *= f0; aa.y *= f0; x[tid]       = aa;
        float2 bb = x[tid + 512]; bb.x *= f1; bb.y *= f1; x[tid + 512] = bb;
    }
    __syncthreads();
    #pragma unroll
    for (int stage = 0; stage < 10; ++stage) {
        const int s  = 1 << stage;
        const int q  = tid & (s - 1);
        const int ps = tid - q;
        float2 aa = x[tid];
        float2 bb = x[tid + 512];
        float2 w = tw[ps]; w.y = -w.y;
        y[2 * ps + q]     = make_float2(aa.x + bb.x, aa.y + bb.y);
        y[2 * ps + s + q] = cmulf(make_float2(aa.x - bb.x, aa.y - bb.y), w);
        __syncthreads();
        float2* t = x; x = y; y = t;
    }

    // Store fp16 v and d into planar arrays: bin record = uint4, slot p = pair m&3,
    // low half = batch 2m (re), high half = 2m+1 (im).
    const float invN = 1.0f / (float)ND;
    const int g2 = m >> 2;
    const int p  = m & 3;
    unsigned int* ov = (unsigned int*)g_v;
    unsigned int* od = (unsigned int*)g_d;
    const size_t base_u = ((size_t)(g2 * NA + a) * ND) * 4;

    {   // bin = tid
        float2 c  = x[tid];
        float2 cn = x[tid + 1];
        ov[base_u + (size_t)tid * 4 + p] =
            h2_as_u32(__floats2half2_rn(c.x * invN, c.y * invN));
        od[base_u + (size_t)tid * 4 + p] =
            h2_as_u32(__floats2half2_rn((cn.x - c.x) * invN, (cn.y - c.y) * invN));
    }
    {   // bin = tid + 512
        float2 c  = x[tid + 512];
        float2 cn = (tid < 511) ? x[tid + 513] : c;   // d(1023) never read
        ov[base_u + (size_t)(tid + 512) * 4 + p] =
            h2_as_u32(__floats2half2_rn(c.x * invN, c.y * invN));
        od[base_u + (size_t)(tid + 512) * 4 + p] =
            h2_as_u32(__floats2half2_rn((cn.x - c.x) * invN, (cn.y - c.y) * invN));
    }
}

// -------------------------------------------------------------------------
// Kernel 2: backprojection. 1 pixel x 8 batches per thread. Per angle:
// 2 LDG.128 (planar v and d records, 16B stride -> ~1.8 lines each),
// 4 HFMA2 + 4 HADD2 fp16 lerp+acc, fp32 flush every 8 angles.
// t in [150.2, 872.8] always -> no bounds checks; t>0 -> (int)t == floor(t).
// -------------------------------------------------------------------------
__global__ __launch_bounds__(256) void fbp_backproj_kernel(float* __restrict__ out)
{
    __shared__ float2 cs[NA];

    const int tid = threadIdx.x;
    for (int i = tid; i < NA; i += 256) {
        float sv, cv;
        sincosf((PI_F / (float)NA) * (float)i, &sv, &cv);
        cs[i] = make_float2(cv, sv);
    }
    __syncthreads();

    const int wrp  = tid >> 5;
    const int lane = tid & 31;
    const int x = (blockIdx.x << 4) + (lane & 7) + ((wrp & 1) << 3);
    const int y = (blockIdx.y << 4) + (lane >> 3) + ((wrp >> 1) << 2);
    const float px = (float)x - 0.5f * (float)(NW - 1);
    const float py = (float)y - 0.5f * (float)(NH - 1);

    const int g2 = blockIdx.z;                       // batches 8*g2 .. 8*g2+7
    const uint4* __restrict__ vbase = g_v + (size_t)g2 * NA * ND;
    const uint4* __restrict__ dbase = g_d + (size_t)g2 * NA * ND;

    float acc[8];
    #pragma unroll
    for (int j = 0; j < 8; ++j) acc[j] = 0.0f;

    for (int a0 = 0; a0 < NA; a0 += 8) {
        __half2 h0 = __float2half2_rn(0.0f);
        __half2 h1 = h0, h2 = h0, h3 = h0;

        #pragma unroll
        for (int k = 0; k < 8; ++k) {
            const int a = a0 + k;
            float2 csa = cs[a];
            float t  = fmaf(px, csa.x, fmaf(py, csa.y, 0.5f * (float)(ND - 1)));
            int   i0 = (int)t;                 // t > 0 -> truncation == floor
            __half2 w2 = __float2half2_rn(t - (float)i0);

            const int off = a * ND + i0;
            uint4 v = vbase[off];
            uint4 d = dbase[off];

            __half2 v0 = *reinterpret_cast<__half2*>(&v.x);
            __half2 v1 = *reinterpret_cast<__half2*>(&v.y);
            __half2 v2 = *reinterpret_cast<__half2*>(&v.z);
            __half2 v3 = *reinterpret_cast<__half2*>(&v.w);
            __half2 d0 = *reinterpret_cast<__half2*>(&d.x);
            __half2 d1 = *reinterpret_cast<__half2*>(&d.y);
            __half2 d2 = *reinterpret_cast<__half2*>(&d.z);
            __half2 d3 = *reinterpret_cast<__half2*>(&d.w);

            h0 = __hadd2(h0, __hfma2(w2, d0, v0));
            h1 = __hadd2(h1, __hfma2(w2, d1, v1));
            h2 = __hadd2(h2, __hfma2(w2, d2, v2));
            h3 = __hadd2(h3, __hfma2(w2, d3, v3));
        }

        acc[0] += __low2float(h0);  acc[1] += __high2float(h0);
        acc[2] += __low2float(h1);  acc[3] += __high2float(h1);
        acc[4] += __low2float(h2);  acc[5] += __high2float(h2);
        acc[6] += __low2float(h3);  acc[7] += __high2float(h3);
    }

    const float scale = PI_F / (float)NA;
    const size_t pix = (size_t)y * NW + x;
    const size_t HW = (size_t)NH * NW;
    float* dst = out + (size_t)(8 * g2) * HW + pix;
    #pragma unroll
    for (int j = 0; j < 8; ++j)
        dst[(size_t)j * HW] = acc[j] * scale;
}

extern "C" void kernel_launch(void* const* d_in, const int* in_sizes, int n_in,
                              void* d_out, int out_size)
{
    const float* sino = (const float*)d_in[0];   // (16, 720, 1024) fp32
    const float* filt = (const float*)d_in[1];   // (1024,) fp32
    float* out = (float*)d_out;                  // (16, 512, 512) fp32

    dim3 fgrid(NA, NB / 2);
    fbp_filter_kernel<<<fgrid, 512>>>(sino, filt);

    dim3 bgrid(NW / 16, NH / 16, 2);
    fbp_backproj_kernel<<<bgrid, 256>>>(out);
}

// round 8
// speedup vs baseline: 1.2163x; 1.2163x over previous
#include <cuda_runtime.h>
#include <cuda_fp16.h>
#include <math.h>

#define NB 16
#define NA 720
#define ND 1024
#define NH 512
#define NW 512
#define PI_F 3.14159265358979323846f

// Filtered sinogram in fp16, planar v / d arrays (16B record per bin = 8 batches).
// g_v[g2][a][bin]: values; g_d[g2][a][bin]: forward differences v[bin+1]-v[bin].
__device__ uint4 g_v[2 * NA * ND];
__device__ uint4 g_d[2 * NA * ND];

__device__ __forceinline__ float2 cmulf(float2 a, float2 b) {
    return make_float2(a.x * b.x - a.y * b.y, a.x * b.y + a.y * b.x);
}
__device__ __forceinline__ unsigned int h2_as_u32(__half2 h) {
    return *reinterpret_cast<unsigned int*>(&h);
}
__device__ __forceinline__ __half2 u32_as_h2(unsigned int u) {
    return *reinterpret_cast<__half2*>(&u);
}

// -------------------------------------------------------------------------
// Kernel 1: ramp filter via complex-pair Stockham FFT (filter real & even:
// FFT(u+iv)*f -> re=filt(u), im=filt(v) exactly). Block = (angle a, batch
// pair m). Stores fp16 v and d into the planar arrays (u32 slot p=m&3).
// -------------------------------------------------------------------------
__global__ __launch_bounds__(512) void fbp_filter_kernel(
    const float* __restrict__ sino, const float* __restrict__ filt)
{
    __shared__ float2 bufA[ND];
    __shared__ float2 bufB[ND];
    __shared__ float2 tw[ND / 2];

    const int a = blockIdx.x;
    const int m = blockIdx.y;       // batches 2m, 2m+1
    const int tid = threadIdx.x;

    const float* u = sino + ((size_t)(2 * m) * NA + a) * ND;
    const float* v = sino + ((size_t)(2 * m + 1) * NA + a) * ND;

    bufA[tid]       = make_float2(u[tid],       v[tid]);
    bufA[tid + 512] = make_float2(u[tid + 512], v[tid + 512]);
    {
        float sv, cv;
        sincosf((-2.0f * PI_F / ND) * (float)tid, &sv, &cv);
        tw[tid] = make_float2(cv, sv);
    }
    __syncthreads();

    float2* x = bufA;
    float2* y = bufB;

    #pragma unroll
    for (int stage = 0; stage < 10; ++stage) {
        const int s  = 1 << stage;
        const int q  = tid & (s - 1);
        const int ps = tid - q;
        float2 aa = x[tid];
        float2 bb = x[tid + 512];
        float2 w = tw[ps];
        y[2 * ps + q]     = make_float2(aa.x + bb.x, aa.y + bb.y);
        y[2 * ps + s + q] = cmulf(make_float2(aa.x - bb.x, aa.y - bb.y), w);
        __syncthreads();
        float2* t = x; x = y; y = t;
    }
    {
        float f0 = filt[tid], f1 = filt[tid + 512];
        float2 aa = x[tid];       aa.x *= f0; aa.y *= f0; x[tid]       = aa;
        float2 bb = x[tid + 512]; bb.x *= f1; bb.y *= f1; x[tid + 512] = bb;
    }
    __syncthreads();
    #pragma unroll
    for (int stage = 0; stage < 10; ++stage) {
        const int s  = 1 << stage;
        const int q  = tid & (s - 1);
        const int ps = tid - q;
        float2 aa = x[tid];
        float2 bb = x[tid + 512];
        float2 w = tw[ps]; w.y = -w.y;
        y[2 * ps + q]     = make_float2(aa.x + bb.x, aa.y + bb.y);
        y[2 * ps + s + q] = cmulf(make_float2(aa.x - bb.x, aa.y - bb.y), w);
        __syncthreads();
        float2* t = x; x = y; y = t;
    }

    const float invN = 1.0f / (float)ND;
    const int g2 = m >> 2;
    const int p  = m & 3;
    unsigned int* ov = (unsigned int*)g_v;
    unsigned int* od = (unsigned int*)g_d;
    const size_t base_u = ((size_t)(g2 * NA + a) * ND) * 4;

    {   // bin = tid
        float2 c  = x[tid];
        float2 cn = x[tid + 1];
        ov[base_u + (size_t)tid * 4 + p] =
            h2_as_u32(__floats2half2_rn(c.x * invN, c.y * invN));
        od[base_u + (size_t)tid * 4 + p] =
            h2_as_u32(__floats2half2_rn((cn.x - c.x) * invN, (cn.y - c.y) * invN));
    }
    {   // bin = tid + 512
        float2 c  = x[tid + 512];
        float2 cn = (tid < 511) ? x[tid + 513] : c;   // d(1023) never read
        ov[base_u + (size_t)(tid + 512) * 4 + p] =
            h2_as_u32(__floats2half2_rn(c.x * invN, c.y * invN));
        od[base_u + (size_t)(tid + 512) * 4 + p] =
            h2_as_u32(__floats2half2_rn((cn.x - c.x) * invN, (cn.y - c.y) * invN));
    }
}

// -------------------------------------------------------------------------
// Kernel 2: backprojection, warp-cooperative loads.
// Warp tile = 8x4 pixels -> per-angle bin footprint <= 7|c|+3|s| <= 7.62
// -> <= 9 distinct i0 values. Lanes 0-15 load v[bmin+lane], lanes 16-31
// load d[bmin+lane-16] (ONE LDG.128/warp-angle = 4 L1 wavefronts vs ~16),
// then each lane fetches its bin via shuffle (identical bits to a direct
// load -> numerics unchanged). bmin = __reduce_min_sync(i0): exact, so
// idx = i0-bmin in [0,8] always; bmin+15 <= 887 < 1024 (t in [150.2,872.8]).
// -------------------------------------------------------------------------
__global__ __launch_bounds__(256) void fbp_backproj_kernel(float* __restrict__ out)
{
    __shared__ float2 cs[NA];

    const int tid = threadIdx.x;
    for (int i = tid; i < NA; i += 256) {
        float sv, cv;
        sincosf((PI_F / (float)NA) * (float)i, &sv, &cv);
        cs[i] = make_float2(cv, sv);
    }
    __syncthreads();

    const int wrp  = tid >> 5;
    const int lane = tid & 31;
    const int x = (blockIdx.x << 4) + (lane & 7) + ((wrp & 1) << 3);
    const int y = (blockIdx.y << 4) + (lane >> 3) + ((wrp >> 1) << 2);
    const float px = (float)x - 0.5f * (float)(NW - 1);
    const float py = (float)y - 0.5f * (float)(NH - 1);

    const int g2 = blockIdx.z;                       // batches 8*g2 .. 8*g2+7
    // Per-lane cooperative-load base: lanes 0-15 -> v array, 16-31 -> d array,
    // each offset by its slot (lane & 15) within the 16-bin window.
    const uint4* __restrict__ lanebase =
        ((lane < 16) ? g_v : g_d) + (size_t)g2 * NA * ND + (lane & 15);

    float acc[8];
    #pragma unroll
    for (int j = 0; j < 8; ++j) acc[j] = 0.0f;

    for (int a0 = 0; a0 < NA; a0 += 8) {
        __half2 h0 = __float2half2_rn(0.0f);
        __half2 h1 = h0, h2 = h0, h3 = h0;

        #pragma unroll
        for (int k = 0; k < 8; ++k) {
            const int a = a0 + k;
            float2 csa = cs[a];
            float t  = fmaf(px, csa.x, fmaf(py, csa.y, 0.5f * (float)(ND - 1)));
            int   i0 = (int)t;                       // t > 0 -> trunc == floor
            int bmin = __reduce_min_sync(0xffffffffu, i0);

            uint4 r = lanebase[a * ND + bmin];       // warp-cooperative load

            __half2 w2 = __float2half2_rn(t - (float)i0);
            int idx  = i0 - bmin;                    // in [0, 8]
            int idxd = idx + 16;

            unsigned vx = __shfl_sync(0xffffffffu, r.x, idx);
            unsigned vy = __shfl_sync(0xffffffffu, r.y, idx);
            unsigned vz = __shfl_sync(0xffffffffu, r.z, idx);
            unsigned vw = __shfl_sync(0xffffffffu, r.w, idx);
            unsigned dx = __shfl_sync(0xffffffffu, r.x, idxd);
            unsigned dy = __shfl_sync(0xffffffffu, r.y, idxd);
            unsigned dz = __shfl_sync(0xffffffffu, r.z, idxd);
            unsigned dw = __shfl_sync(0xffffffffu, r.w, idxd);

            h0 = __hadd2(h0, __hfma2(w2, u32_as_h2(dx), u32_as_h2(vx)));
            h1 = __hadd2(h1, __hfma2(w2, u32_as_h2(dy), u32_as_h2(vy)));
            h2 = __hadd2(h2, __hfma2(w2, u32_as_h2(dz), u32_as_h2(vz)));
            h3 = __hadd2(h3, __hfma2(w2, u32_as_h2(dw), u32_as_h2(vw)));
        }

        acc[0] += __low2float(h0);  acc[1] += __high2float(h0);
        acc[2] += __low2float(h1);  acc[3] += __high2float(h1);
        acc[4] += __low2float(h2);  acc[5] += __high2float(h2);
        acc[6] += __low2float(h3);  acc[7] += __high2float(h3);
    }

    const float scale = PI_F / (float)NA;
    const size_t pix = (size_t)y * NW + x;
    const size_t HW = (size_t)NH * NW;
    float* dst = out + (size_t)(8 * g2) * HW + pix;
    #pragma unroll
    for (int j = 0; j < 8; ++j)
        dst[(size_t)j * HW] = acc[j] * scale;
}

extern "C" void kernel_launch(void* const* d_in, const int* in_sizes, int n_in,
                              void* d_out, int out_size)
{
    const float* sino = (const float*)d_in[0];   // (16, 720, 1024) fp32
    const float* filt = (const float*)d_in[1];   // (1024,) fp32
    float* out = (float*)d_out;                  // (16, 512, 512) fp32

    dim3 fgrid(NA, NB / 2);
    fbp_filter_kernel<<<fgrid, 512>>>(sino, filt);

    dim3 bgrid(NW / 16, NH / 16, 2);
    fbp_backproj_kernel<<<bgrid, 256>>>(out);
}

// round 9
// speedup vs baseline: 1.4394x; 1.1834x over previous
#include <cuda_runtime.h>
#include <cuda_fp16.h>
#include <math.h>

#define NB 16
#define NA 720
#define ND 1024
#define NH 512
#define NW 512
#define PI_F 3.14159265358979323846f

// Filtered sinogram in fp16: g_v[g2][a][bin] = uint4 record of 8 batches
// (batches 8*g2 .. 8*g2+7, stored as 4 half2). 23.6 MB, L2-resident.
__device__ uint4 g_v[2 * NA * ND];

__device__ __forceinline__ float2 cmulf(float2 a, float2 b) {
    return make_float2(a.x * b.x - a.y * b.y, a.x * b.y + a.y * b.x);
}
__device__ __forceinline__ unsigned int h2_as_u32(__half2 h) {
    return *reinterpret_cast<unsigned int*>(&h);
}
__device__ __forceinline__ __half2 u32_as_h2(unsigned int u) {
    return *reinterpret_cast<__half2*>(&u);
}

// -------------------------------------------------------------------------
// Kernel 1: ramp filter via complex-pair Stockham FFT (filter real & even:
// FFT(u+iv)*f -> re=filt(u), im=filt(v) exactly). Block = (angle a, batch
// pair m). Stores fp16 v into planar array (u32 slot p = m&3).
// -------------------------------------------------------------------------
__global__ __launch_bounds__(512) void fbp_filter_kernel(
    const float* __restrict__ sino, const float* __restrict__ filt)
{
    __shared__ float2 bufA[ND];
    __shared__ float2 bufB[ND];
    __shared__ float2 tw[ND / 2];

    const int a = blockIdx.x;
    const int m = blockIdx.y;       // batches 2m, 2m+1
    const int tid = threadIdx.x;

    const float* u = sino + ((size_t)(2 * m) * NA + a) * ND;
    const float* v = sino + ((size_t)(2 * m + 1) * NA + a) * ND;

    bufA[tid]       = make_float2(u[tid],       v[tid]);
    bufA[tid + 512] = make_float2(u[tid + 512], v[tid + 512]);
    {
        float sv, cv;
        sincosf((-2.0f * PI_F / ND) * (float)tid, &sv, &cv);
        tw[tid] = make_float2(cv, sv);
    }
    __syncthreads();

    float2* x = bufA;
    float2* y = bufB;

    #pragma unroll
    for (int stage = 0; stage < 10; ++stage) {
        const int s  = 1 << stage;
        const int q  = tid & (s - 1);
        const int ps = tid - q;
        float2 aa = x[tid];
        float2 bb = x[tid + 512];
        float2 w = tw[ps];
        y[2 * ps + q]     = make_float2(aa.x + bb.x, aa.y + bb.y);
        y[2 * ps + s + q] = cmulf(make_float2(aa.x - bb.x, aa.y - bb.y), w);
        __syncthreads();
        float2* t = x; x = y; y = t;
    }
    {
        float f0 = filt[tid], f1 = filt[tid + 512];
        float2 aa = x[tid];       aa.x *= f0; aa.y *= f0; x[tid]       = aa;
        float2 bb = x[tid + 512]; bb.x *= f1; bb.y *= f1; x[tid + 512] = bb;
    }
    __syncthreads();
    #pragma unroll
    for (int stage = 0; stage < 10; ++stage) {
        const int s  = 1 << stage;
        const int q  = tid & (s - 1);
        const int ps = tid - q;
        float2 aa = x[tid];
        float2 bb = x[tid + 512];
        float2 w = tw[ps]; w.y = -w.y;
        y[2 * ps + q]     = make_float2(aa.x + bb.x, aa.y + bb.y);
        y[2 * ps + s + q] = cmulf(make_float2(aa.x - bb.x, aa.y - bb.y), w);
        __syncthreads();
        float2* t = x; x = y; y = t;
    }

    const float invN = 1.0f / (float)ND;
    const int g2 = m >> 2;
    const int p  = m & 3;
    unsigned int* ov = (unsigned int*)g_v;
    const size_t base_u = ((size_t)(g2 * NA + a) * ND) * 4;

    {   // bin = tid
        float2 c = x[tid];
        ov[base_u + (size_t)tid * 4 + p] =
            h2_as_u32(__floats2half2_rn(c.x * invN, c.y * invN));
    }
    {   // bin = tid + 512
        float2 c = x[tid + 512];
        ov[base_u + (size_t)(tid + 512) * 4 + p] =
            h2_as_u32(__floats2half2_rn(c.x * invN, c.y * invN));
    }
}

// -------------------------------------------------------------------------
// Kernel 2: backprojection, warp-cooperative v-window + angle pairing.
// Warp tile 8x4 -> per-angle footprint <= 7|c|+3|s| <= 7.62 bins.
// One LDG per TWO angles: lanes 0-15 hold angle k's 16-bin window,
// lanes 16-31 angle k+1's. v(i0) and v(i0+1) both come from the window
// via shuffle; d computed in fp16 (HSUB2).
// bmin analytic (no REDUX): s>=0 so y-min at tile top; x-corner by sign
// of c; -1 safety margin -> idx in [0,10], idx+1 <= 11 <= 15. Bounds:
// bmin in [149, 871], bmin+15 <= 886 < 1024.
// -------------------------------------------------------------------------
__global__ __launch_bounds__(256) void fbp_backproj_kernel(float* __restrict__ out)
{
    __shared__ float4 cs2[NA / 2];   // (c0,s0,c1,s1) per angle pair

    const int tid = threadIdx.x;
    for (int i = tid; i < NA / 2; i += 256) {
        float s0, c0, s1, c1;
        sincosf((PI_F / (float)NA) * (float)(2 * i),     &s0, &c0);
        sincosf((PI_F / (float)NA) * (float)(2 * i + 1), &s1, &c1);
        cs2[i] = make_float4(c0, s0, c1, s1);
    }
    __syncthreads();

    const int wrp  = tid >> 5;
    const int lane = tid & 31;
    const int xb = (blockIdx.x << 4) + ((wrp & 1) << 3);
    const int yb = (blockIdx.y << 4) + ((wrp >> 1) << 2);
    const int x = xb + (lane & 7);
    const int y = yb + (lane >> 3);
    const float px  = (float)x - 0.5f * (float)(NW - 1);
    const float py  = (float)y - 0.5f * (float)(NH - 1);
    const float pxb = (float)xb - 0.5f * (float)(NW - 1);
    const float pyb = (float)yb - 0.5f * (float)(NH - 1);
    const float C   = 0.5f * (float)(ND - 1);

    const int g2 = blockIdx.z;                       // batches 8*g2 .. 8*g2+7
    const uint4* __restrict__ vbase = g_v + (size_t)g2 * NA * ND;
    const int lanehalf = lane >> 4;                  // 0: angle k, 1: angle k+1
    const int lanelow  = lane & 15;

    float acc[8];
    #pragma unroll
    for (int j = 0; j < 8; ++j) acc[j] = 0.0f;

    for (int a0 = 0; a0 < NA; a0 += 8) {
        __half2 h0 = __float2half2_rn(0.0f);
        __half2 h1 = h0, h2 = h0, h3 = h0;

        #pragma unroll
        for (int j = 0; j < 4; ++j) {
            const int a = a0 + 2 * j;
            float4 q = cs2[(a0 >> 1) + j];           // LDS.128 broadcast

            // analytic window minima (warp-uniform values, computed per lane)
            float pxm0 = (q.x < 0.0f) ? pxb + 7.0f : pxb;
            float pxm1 = (q.z < 0.0f) ? pxb + 7.0f : pxb;
            int bmin0 = (int)fmaf(pxm0, q.x, fmaf(pyb, q.y, C)) - 1;
            int bmin1 = (int)fmaf(pxm1, q.z, fmaf(pyb, q.w, C)) - 1;

            // paired cooperative load: one LDG serves two angles
            int asel = a + lanehalf;
            int bsel = lanehalf ? bmin1 : bmin0;
            uint4 r = vbase[asel * ND + bsel + lanelow];

            // ---- angle a (window in lanes 0-15) ----
            {
                float t  = fmaf(px, q.x, fmaf(py, q.y, C));
                int   i0 = (int)t;
                __half2 w2 = __float2half2_rn(t - (float)i0);
                int s0i = i0 - bmin0;                // in [0,10]
                int s1i = s0i + 1;

                __half2 vx = u32_as_h2(__shfl_sync(0xffffffffu, r.x, s0i));
                __half2 vy = u32_as_h2(__shfl_sync(0xffffffffu, r.y, s0i));
                __half2 vz = u32_as_h2(__shfl_sync(0xffffffffu, r.z, s0i));
                __half2 vw = u32_as_h2(__shfl_sync(0xffffffffu, r.w, s0i));
                __half2 ux = u32_as_h2(__shfl_sync(0xffffffffu, r.x, s1i));
                __half2 uy = u32_as_h2(__shfl_sync(0xffffffffu, r.y, s1i));
                __half2 uz = u32_as_h2(__shfl_sync(0xffffffffu, r.z, s1i));
                __half2 uw = u32_as_h2(__shfl_sync(0xffffffffu, r.w, s1i));

                h0 = __hadd2(h0, __hfma2(w2, __hsub2(ux, vx), vx));
                h1 = __hadd2(h1, __hfma2(w2, __hsub2(uy, vy), vy));
                h2 = __hadd2(h2, __hfma2(w2, __hsub2(uz, vz), vz));
                h3 = __hadd2(h3, __hfma2(w2, __hsub2(uw, vw), vw));
            }
            // ---- angle a+1 (window in lanes 16-31) ----
            {
                float t  = fmaf(px, q.z, fmaf(py, q.w, C));
                int   i0 = (int)t;
                __half2 w2 = __float2half2_rn(t - (float)i0);
                int s0i = 16 + i0 - bmin1;           // in [16,26]
                int s1i = s0i + 1;

                __half2 vx = u32_as_h2(__shfl_sync(0xffffffffu, r.x, s0i));
                __half2 vy = u32_as_h2(__shfl_sync(0xffffffffu, r.y, s0i));
                __half2 vz = u32_as_h2(__shfl_sync(0xffffffffu, r.z, s0i));
                __half2 vw = u32_as_h2(__shfl_sync(0xffffffffu, r.w, s0i));
                __half2 ux = u32_as_h2(__shfl_sync(0xffffffffu, r.x, s1i));
                __half2 uy = u32_as_h2(__shfl_sync(0xffffffffu, r.y, s1i));
                __half2 uz = u32_as_h2(__shfl_sync(0xffffffffu, r.z, s1i));
                __half2 uw = u32_as_h2(__shfl_sync(0xffffffffu, r.w, s1i));

                h0 = __hadd2(h0, __hfma2(w2, __hsub2(ux, vx), vx));
                h1 = __hadd2(h1, __hfma2(w2, __hsub2(uy, vy), vy));
                h2 = __hadd2(h2, __hfma2(w2, __hsub2(uz, vz), vz));
                h3 = __hadd2(h3, __hfma2(w2, __hsub2(uw, vw), vw));
            }
        }

        acc[0] += __low2float(h0);  acc[1] += __high2float(h0);
        acc[2] += __low2float(h1);  acc[3] += __high2float(h1);
        acc[4] += __low2float(h2);  acc[5] += __high2float(h2);
        acc[6] += __low2float(h3);  acc[7] += __high2float(h3);
    }

    const float scale = PI_F / (float)NA;
    const size_t pix = (size_t)y * NW + x;
    const size_t HW = (size_t)NH * NW;
    float* dst = out + (size_t)(8 * g2) * HW + pix;
    #pragma unroll
    for (int j = 0; j < 8; ++j)
        dst[(size_t)j * HW] = acc[j] * scale;
}

extern "C" void kernel_launch(void* const* d_in, const int* in_sizes, int n_in,
                              void* d_out, int out_size)
{
    const float* sino = (const float*)d_in[0];   // (16, 720, 1024) fp32
    const float* filt = (const float*)d_in[1];   // (1024,) fp32
    float* out = (float*)d_out;                  // (16, 512, 512) fp32

    dim3 fgrid(NA, NB / 2);
    fbp_filter_kernel<<<fgrid, 512>>>(sino, filt);

    dim3 bgrid(NW / 16, NH / 16, 2);
    fbp_backproj_kernel<<<bgrid, 256>>>(out);
}